// round 2
// baseline (speedup 1.0000x reference)
#include <cuda_runtime.h>
#include <stdint.h>

// HypervectorEngine: 512x8192 f32 signal -> 512x4096 f32 sparse sign output.
// Replicates JAX threefry2x32 RNG exactly.
//
// RNG variant selection:
//   3: partitionable (JAX >= 0.4.36 default): word_j = o0 ^ o1 of threefry(key,(0,j))  <-- primary
//   0: word_j = o0 only
//   1: word_j = o1 only
//   2: legacy split-halves (partitionable=False)
#define RNG_VARIANT 3

#define NSAMP    100
#define DIMV     4096
#define KSEL     2048
#define LSIG     8192
#define NTHREADS 256
#define JPT      (DIMV / NTHREADS)   // 16 contiguous j's per thread

__device__ __forceinline__ void tf_round(uint32_t& x0, uint32_t& x1, const int r) {
    x0 += x1;
    x1 = __funnelshift_l(x1, x1, r);   // rotl
    x1 ^= x0;
}

// JAX threefry2x32 (20 rounds, rotations [13,15,26,6]/[17,29,16,24], 0x1BD11BDA)
__device__ __forceinline__ void threefry2x32_full(
    uint32_t k0, uint32_t k1, uint32_t k2, uint32_t c0, uint32_t c1,
    uint32_t& o0, uint32_t& o1)
{
    uint32_t x0 = c0 + k0, x1 = c1 + k1;
    tf_round(x0, x1, 13); tf_round(x0, x1, 15); tf_round(x0, x1, 26); tf_round(x0, x1, 6);
    x0 += k1; x1 += k2 + 1u;
    tf_round(x0, x1, 17); tf_round(x0, x1, 29); tf_round(x0, x1, 16); tf_round(x0, x1, 24);
    x0 += k2; x1 += k0 + 2u;
    tf_round(x0, x1, 13); tf_round(x0, x1, 15); tf_round(x0, x1, 26); tf_round(x0, x1, 6);
    x0 += k0; x1 += k1 + 3u;
    tf_round(x0, x1, 17); tf_round(x0, x1, 29); tf_round(x0, x1, 16); tf_round(x0, x1, 24);
    x0 += k1; x1 += k2 + 4u;
    tf_round(x0, x1, 13); tf_round(x0, x1, 15); tf_round(x0, x1, 26); tf_round(x0, x1, 6);
    o0 = x0 + k2;
    o1 = x1 + k0 + 5u;
}

__global__ void __launch_bounds__(NTHREADS)
hv_engine_kernel(const float* __restrict__ sig, float* __restrict__ out)
{
    const int b = blockIdx.x;
    const int t = threadIdx.x;

    __shared__ uint32_t skey0[NSAMP];
    __shared__ uint32_t skey1[NSAMP];
    __shared__ int      shist[51];
    __shared__ int      sscan[NTHREADS];
    __shared__ int      sT, sQuota;
#if RNG_VARIANT == 2
    __shared__ int8_t   scmb[DIMV];
#endif

    // ---- per-sample keys: key_i = threefry((0,42), (0, i ^ rint(sig*1000))) ----
    if (t < NSAMP) {
        const int i   = t;
        const int idx = (i * (LSIG - 1)) / (NSAMP - 1);   // == trunc of f32 linspace (safe: err << 1/99)
        const float s = sig[(size_t)b * LSIG + idx];
        const int val = __float2int_rn(s * 1000.0f);      // jnp.round (RNE) then int cast
        const uint32_t seed = (uint32_t)(i ^ val);
        const uint32_t bk2 = 0u ^ 42u ^ 0x1BD11BDAu;
        uint32_t o0, o1;
        threefry2x32_full(0u, 42u, bk2, 0u, seed, o0, o1);
        skey0[i] = o0;
        skey1[i] = o1;
    }
    if (t < 51) shist[t] = 0;
    __syncthreads();

    // ---- main hash loop: combined[j] = sum_i (msb(word_ij) ? -1 : +1) ----
    int msbcnt[JPT];
#pragma unroll
    for (int q = 0; q < JPT; q++) msbcnt[q] = 0;

#if RNG_VARIANT == 2
    const uint32_t pbase = (uint32_t)t * (JPT / 2);   // 8 pairs per thread, pairs (p, p+2048)
    int msbcnt2[JPT / 2];
#pragma unroll
    for (int q = 0; q < JPT / 2; q++) msbcnt2[q] = 0;
#endif
    const uint32_t jbase = (uint32_t)t * JPT;

    for (int i = 0; i < NSAMP; i++) {
        const uint32_t k0 = skey0[i];
        const uint32_t k1 = skey1[i];
        const uint32_t k2 = k0 ^ k1 ^ 0x1BD11BDAu;
#if RNG_VARIANT == 2
#pragma unroll
        for (int q = 0; q < JPT / 2; q++) {
            uint32_t o0, o1;
            threefry2x32_full(k0, k1, k2, pbase + q, pbase + q + 2048u, o0, o1);
            msbcnt[q]  += (int)(o0 >> 31);
            msbcnt2[q] += (int)(o1 >> 31);
        }
#else
#pragma unroll
        for (int q = 0; q < JPT; q++) {
            uint32_t o0, o1;
            threefry2x32_full(k0, k1, k2, 0u, jbase + q, o0, o1);
#if RNG_VARIANT == 3
            msbcnt[q] += (int)((o0 ^ o1) >> 31);   // partitionable: bits = o0 ^ o1
#elif RNG_VARIANT == 0
            msbcnt[q] += (int)(o0 >> 31);
            (void)o1;
#else
            msbcnt[q] += (int)(o1 >> 31);
            (void)o0;
#endif
        }
#endif
    }

    // combined values for this thread's 16 contiguous j's
    int cval[JPT];
#if RNG_VARIANT == 2
    {
#pragma unroll
        for (int q = 0; q < JPT / 2; q++) {
            scmb[pbase + q]         = (int8_t)(NSAMP - 2 * msbcnt[q]);
            scmb[pbase + q + 2048u] = (int8_t)(NSAMP - 2 * msbcnt2[q]);
        }
        __syncthreads();
#pragma unroll
        for (int q = 0; q < JPT; q++) cval[q] = (int)scmb[jbase + q];
    }
#else
#pragma unroll
    for (int q = 0; q < JPT; q++) cval[q] = NSAMP - 2 * msbcnt[q];
#endif

    // ---- histogram of |combined| (even, 0..100 -> 51 bins) ----
#pragma unroll
    for (int q = 0; q < JPT; q++) {
        int a = cval[q] < 0 ? -cval[q] : cval[q];
        atomicAdd(&shist[a >> 1], 1);
    }
    __syncthreads();

    // ---- threshold T and tie quota (top-k = 2048, ties by lowest index) ----
    if (t == 0) {
        int cum = 0, T = 0, quota = 0;
        for (int v = 50; v >= 0; v--) {
            int h = shist[v];
            if (cum + h >= KSEL) { T = v * 2; quota = KSEL - cum; break; }
            cum += h;
        }
        sT = T; sQuota = quota;
    }
    __syncthreads();
    const int T = sT, quota = sQuota;

    // ---- ordered block scan of (|c|==T) to replicate stable tie-break ----
    int eq = 0;
#pragma unroll
    for (int q = 0; q < JPT; q++) {
        int a = cval[q] < 0 ? -cval[q] : cval[q];
        eq += (a == T);
    }
    sscan[t] = eq;
    __syncthreads();
    for (int off = 1; off < NTHREADS; off <<= 1) {
        int v = sscan[t];
        int add = (t >= off) ? sscan[t - off] : 0;
        __syncthreads();
        sscan[t] = v + add;
        __syncthreads();
    }
    int rank = sscan[t] - eq;   // exclusive prefix = global tie rank base

    // ---- write output ----
    float* orow = out + (size_t)b * DIMV;
#pragma unroll
    for (int q = 0; q < JPT; q++) {
        const int c = cval[q];
        const int a = c < 0 ? -c : c;
        float v = 0.0f;
        if (a > T) {
            v = (c > 0) ? 1.0f : -1.0f;
        } else if (a == T) {
            if (rank < quota) v = (c > 0) ? 1.0f : ((c < 0) ? -1.0f : 0.0f);
            rank++;   // ties consume quota in index order (incl. zeros when T==0)
        }
        orow[jbase + q] = v;
    }
}

extern "C" void kernel_launch(void* const* d_in, const int* in_sizes, int n_in,
                              void* d_out, int out_size)
{
    const float* sig = (const float*)d_in[0];
    float* out = (float*)d_out;
    const int B = in_sizes[0] / LSIG;   // 512
    hv_engine_kernel<<<B, NTHREADS>>>(sig, out);
}

// round 3
// speedup vs baseline: 1.1068x; 1.1068x over previous
#include <cuda_runtime.h>
#include <stdint.h>

// HypervectorEngine: 512x8192 f32 -> 512x4096 f32 sparse sign output.
// Two-phase: (A) threefry hash counts, pipe-balanced IMAD/alu; (B) top-k select.
// RNG: JAX partitionable threefry, word_j = o0 ^ o1 of threefry(key,(0,j)). (verified R2)

#define NSAMP    100
#define DIMV     4096
#define KSEL     2048
#define LSIG     8192
#define NROWS    512

#define SPLIT    2                    // CTAs per row in hash phase
#define A_THREADS 128
#define A_JPT    (DIMV / SPLIT / A_THREADS)   // 16

#define B_THREADS 256
#define B_JPT    (DIMV / B_THREADS)           // 16

__device__ int8_t g_cval[(size_t)NROWS * DIMV];

// Force add onto the FMA pipe: d = a*one + b, 'one' is runtime-opaque.
__device__ __forceinline__ uint32_t addi(uint32_t a, uint32_t b, uint32_t one) {
    uint32_t d;
    asm("mad.lo.u32 %0, %1, %2, %3;" : "=r"(d) : "r"(a), "r"(one), "r"(b));
    return d;
}
// Same, immediate addend (for x1 init: k1jb + q).
template <int IMM>
__device__ __forceinline__ uint32_t addi_c(uint32_t a, uint32_t one) {
    uint32_t d;
    asm("mad.lo.u32 %0, %1, %2, %3;" : "=r"(d) : "r"(a), "r"(one), "n"(IMM));
    return d;
}

__device__ __forceinline__ void tf_round(uint32_t& x0, uint32_t& x1, const int r, uint32_t one) {
    x0 = addi(x0, x1, one);            // IMAD (fma pipe)
    x1 = __funnelshift_l(x1, x1, r);   // SHF  (alu)
    x1 ^= x0;                          // LOP3 (alu)
}

// Full threefry for the per-sample key derivation (cold path, plain C adds fine).
__device__ __forceinline__ void threefry_key(
    uint32_t c1, uint32_t& o0, uint32_t& o1)
{
    const uint32_t k0 = 0u, k1 = 42u, k2 = 0u ^ 42u ^ 0x1BD11BDAu;
    uint32_t x0 = k0, x1 = c1 + k1;
    #define R(r) { x0 += x1; x1 = __funnelshift_l(x1, x1, r); x1 ^= x0; }
    R(13) R(15) R(26) R(6)  x0 += k1; x1 += k2 + 1u;
    R(17) R(29) R(16) R(24) x0 += k2; x1 += k0 + 2u;
    R(13) R(15) R(26) R(6)  x0 += k0; x1 += k1 + 3u;
    R(17) R(29) R(16) R(24) x0 += k1; x1 += k2 + 4u;
    R(13) R(15) R(26) R(6)
    o0 = x0 + k2; o1 = x1 + k0 + 5u;
    #undef R
}

// ---------------- Phase A: hash counts ----------------
__global__ void __launch_bounds__(A_THREADS)
hv_hash_kernel(const float* __restrict__ sig, uint32_t one)
{
    const int bid  = blockIdx.x;
    const int row  = bid >> 1;
    const int part = bid & 1;
    const int t    = threadIdx.x;

    __shared__ uint32_t skey0[NSAMP];
    __shared__ uint32_t skey1[NSAMP];

    if (t < NSAMP) {
        const int i   = t;
        const int idx = (i * (LSIG - 1)) / (NSAMP - 1);   // trunc of f32 linspace
        const float s = sig[(size_t)row * LSIG + idx];
        const int val = __float2int_rn(s * 1000.0f);      // jnp.round RNE
        uint32_t o0, o1;
        threefry_key((uint32_t)(i ^ val), o0, o1);
        skey0[i] = o0;
        skey1[i] = o1;
    }
    __syncthreads();

    const uint32_t jbase = (uint32_t)(part * (DIMV / SPLIT) + t * A_JPT);
    const uint32_t two = one + one;

    int cnt[A_JPT];
#pragma unroll
    for (int q = 0; q < A_JPT; q++) cnt[q] = 0;

    for (int i = 0; i < NSAMP; i++) {
        const uint32_t k0 = skey0[i];
        const uint32_t k1 = skey1[i];
        const uint32_t k2   = k0 ^ k1 ^ 0x1BD11BDAu;
        const uint32_t k1jb = k1 + jbase;     // per-i uniform precompute
        const uint32_t k2p1 = k2 + 1u;
        const uint32_t k0p2 = k0 + 2u;
        const uint32_t k1p3 = k1 + 3u;
        const uint32_t k2p4 = k2 + 4u;
        const uint32_t k0p5 = k0 + 5u;

#pragma unroll
        for (int q = 0; q < A_JPT; q++) {
            uint32_t x0 = k0;                 // c0 = 0
            uint32_t x1;
            switch (q) {  // immediate-addend IMAD init (compile-time q)
                case 0:  x1 = addi_c<0 >(k1jb, one); break;
                case 1:  x1 = addi_c<1 >(k1jb, one); break;
                case 2:  x1 = addi_c<2 >(k1jb, one); break;
                case 3:  x1 = addi_c<3 >(k1jb, one); break;
                case 4:  x1 = addi_c<4 >(k1jb, one); break;
                case 5:  x1 = addi_c<5 >(k1jb, one); break;
                case 6:  x1 = addi_c<6 >(k1jb, one); break;
                case 7:  x1 = addi_c<7 >(k1jb, one); break;
                case 8:  x1 = addi_c<8 >(k1jb, one); break;
                case 9:  x1 = addi_c<9 >(k1jb, one); break;
                case 10: x1 = addi_c<10>(k1jb, one); break;
                case 11: x1 = addi_c<11>(k1jb, one); break;
                case 12: x1 = addi_c<12>(k1jb, one); break;
                case 13: x1 = addi_c<13>(k1jb, one); break;
                case 14: x1 = addi_c<14>(k1jb, one); break;
                default: x1 = addi_c<15>(k1jb, one); break;
            }
            tf_round(x0, x1, 13, one); tf_round(x0, x1, 15, one);
            tf_round(x0, x1, 26, one); tf_round(x0, x1, 6,  one);
            x0 = addi(x0, k1, one); x1 = addi(x1, k2p1, one);
            tf_round(x0, x1, 17, one); tf_round(x0, x1, 29, one);
            tf_round(x0, x1, 16, one); tf_round(x0, x1, 24, one);
            x0 = addi(x0, k2, one); x1 = addi(x1, k0p2, one);
            tf_round(x0, x1, 13, one); tf_round(x0, x1, 15, one);
            tf_round(x0, x1, 26, one); tf_round(x0, x1, 6,  one);
            x0 = addi(x0, k0, one); x1 = addi(x1, k1p3, one);
            tf_round(x0, x1, 17, one); tf_round(x0, x1, 29, one);
            tf_round(x0, x1, 16, one); tf_round(x0, x1, 24, one);
            x0 = addi(x0, k1, one); x1 = addi(x1, k2p4, one);
            tf_round(x0, x1, 13, one); tf_round(x0, x1, 15, one);
            tf_round(x0, x1, 26, one); tf_round(x0, x1, 6,  one);
            const uint32_t o0 = addi(x0, k2, one);
            const uint32_t o1 = addi(x1, k0p5, one);
            const uint32_t w  = o0 ^ o1;      // partitionable fold
            // cnt += bit31(w) == hi32(w*2), single IMAD.HI on fma pipe
            asm("mad.hi.u32 %0, %1, %2, %0;" : "+r"(cnt[q]) : "r"(w), "r"(two));
        }
    }

    int8_t* crow = g_cval + (size_t)row * DIMV + jbase;
#pragma unroll
    for (int q = 0; q < A_JPT; q++)
        crow[q] = (int8_t)(NSAMP - 2 * cnt[q]);
}

// ---------------- Phase B: top-k select ----------------
__global__ void __launch_bounds__(B_THREADS)
hv_select_kernel(float* __restrict__ out)
{
    const int b = blockIdx.x;
    const int t = threadIdx.x;

    __shared__ int shist[51];
    __shared__ int sscan[B_THREADS];
    __shared__ int sT, sQuota;

    if (t < 51) shist[t] = 0;
    __syncthreads();

    const int jbase = t * B_JPT;
    const int8_t* crow = g_cval + (size_t)b * DIMV + jbase;

    int cval[B_JPT];
    {   // 16 contiguous bytes, one 128-bit load
        const int4 v = *reinterpret_cast<const int4*>(crow);
        const int8_t* p = reinterpret_cast<const int8_t*>(&v);
#pragma unroll
        for (int q = 0; q < B_JPT; q++) cval[q] = (int)p[q];
    }

#pragma unroll
    for (int q = 0; q < B_JPT; q++) {
        int a = cval[q] < 0 ? -cval[q] : cval[q];
        atomicAdd(&shist[a >> 1], 1);
    }
    __syncthreads();

    if (t == 0) {
        int cum = 0, T = 0, quota = 0;
        for (int v = 50; v >= 0; v--) {
            int h = shist[v];
            if (cum + h >= KSEL) { T = v * 2; quota = KSEL - cum; break; }
            cum += h;
        }
        sT = T; sQuota = quota;
    }
    __syncthreads();
    const int T = sT, quota = sQuota;

    int eq = 0;
#pragma unroll
    for (int q = 0; q < B_JPT; q++) {
        int a = cval[q] < 0 ? -cval[q] : cval[q];
        eq += (a == T);
    }
    sscan[t] = eq;
    __syncthreads();
    for (int off = 1; off < B_THREADS; off <<= 1) {
        int v = sscan[t];
        int add = (t >= off) ? sscan[t - off] : 0;
        __syncthreads();
        sscan[t] = v + add;
        __syncthreads();
    }
    int rank = sscan[t] - eq;   // stable tie rank base (index order)

    float* orow = out + (size_t)b * DIMV + jbase;
#pragma unroll
    for (int q = 0; q < B_JPT; q++) {
        const int c = cval[q];
        const int a = c < 0 ? -c : c;
        float v = 0.0f;
        if (a > T) {
            v = (c > 0) ? 1.0f : -1.0f;
        } else if (a == T) {
            if (rank < quota) v = (c > 0) ? 1.0f : ((c < 0) ? -1.0f : 0.0f);
            rank++;
        }
        orow[q] = v;
    }
}

extern "C" void kernel_launch(void* const* d_in, const int* in_sizes, int n_in,
                              void* d_out, int out_size)
{
    const float* sig = (const float*)d_in[0];
    float* out = (float*)d_out;
    const int B = in_sizes[0] / LSIG;   // 512
    hv_hash_kernel<<<B * SPLIT, A_THREADS>>>(sig, 1u);
    hv_select_kernel<<<B, B_THREADS>>>(out);
}

// round 4
// speedup vs baseline: 17.6440x; 15.9411x over previous
#include <cuda_runtime.h>
#include <stdint.h>

// HypervectorEngine: 512x8192 f32 -> 512x4096 f32 sparse sign output.
// Key insight: seed = i ^ round(sig*1000) in [0,1024) -> only 1024 distinct
// hypervectors exist. Build a bit-packed table once (4.2M hashes), then
// combine per-row with bit-sliced popcount counters.
// RNG: JAX partitionable threefry, word_j = o0 ^ o1 of threefry(key,(0,j)). (verified R2)

#define NSAMP   100
#define DIMV    4096
#define KSEL    2048
#define LSIG    8192
#define NSEEDS  1024
#define WPR     (DIMV / 32)        // 128 packed words per hypervector

// bit l of g_hv[seed*WPR + w]  <->  hv bit for j = w*32 + l  (1 = msb set = -1)
__device__ uint32_t g_hv[NSEEDS * WPR];

// JAX threefry2x32, key (0,42), counter (0,c1) -> derived key (fold_in)
__device__ __forceinline__ void threefry_key(uint32_t c1, uint32_t& o0, uint32_t& o1)
{
    const uint32_t k0 = 0u, k1 = 42u, k2 = 0u ^ 42u ^ 0x1BD11BDAu;
    uint32_t x0 = k0, x1 = c1 + k1;
    #define R(r) { x0 += x1; x1 = __funnelshift_l(x1, x1, r); x1 ^= x0; }
    R(13) R(15) R(26) R(6)  x0 += k1; x1 += k2 + 1u;
    R(17) R(29) R(16) R(24) x0 += k2; x1 += k0 + 2u;
    R(13) R(15) R(26) R(6)  x0 += k0; x1 += k1 + 3u;
    R(17) R(29) R(16) R(24) x0 += k1; x1 += k2 + 4u;
    R(13) R(15) R(26) R(6)
    o0 = x0 + k2; o1 = x1 + k0 + 5u;
    #undef R
}

// General threefry with derived key, counter (0, c1)
__device__ __forceinline__ void threefry_full(
    uint32_t k0, uint32_t k1, uint32_t k2, uint32_t c1, uint32_t& o0, uint32_t& o1)
{
    uint32_t x0 = k0, x1 = c1 + k1;
    #define R(r) { x0 += x1; x1 = __funnelshift_l(x1, x1, r); x1 ^= x0; }
    R(13) R(15) R(26) R(6)  x0 += k1; x1 += k2 + 1u;
    R(17) R(29) R(16) R(24) x0 += k2; x1 += k0 + 2u;
    R(13) R(15) R(26) R(6)  x0 += k0; x1 += k1 + 3u;
    R(17) R(29) R(16) R(24) x0 += k1; x1 += k2 + 4u;
    R(13) R(15) R(26) R(6)
    o0 = x0 + k2; o1 = x1 + k0 + 5u;
    #undef R
}

// ---------------- Kernel 1: build hypervector sign table ----------------
__global__ void __launch_bounds__(256)
hv_table_kernel()
{
    const int seed = blockIdx.x;
    const int t    = threadIdx.x;
    const int lane = t & 31;
    const int wrp  = t >> 5;           // 0..7

    __shared__ uint32_t sk0, sk1;
    if (t == 0) {
        uint32_t o0, o1;
        threefry_key((uint32_t)seed, o0, o1);
        sk0 = o0; sk1 = o1;
    }
    __syncthreads();
    const uint32_t k0 = sk0, k1 = sk1, k2 = k0 ^ k1 ^ 0x1BD11BDAu;

    uint32_t* dst = g_hv + (size_t)seed * WPR;
#pragma unroll
    for (int p = 0; p < DIMV / 256; p++) {       // 16 passes
        const uint32_t j = (uint32_t)(p * 256 + t);
        uint32_t o0, o1;
        threefry_full(k0, k1, k2, j, o0, o1);
        const uint32_t word = __ballot_sync(0xFFFFFFFFu, (int)((o0 ^ o1) >> 31));
        if (lane == 0) dst[p * 8 + wrp] = word;  // word index = j/32, bit = j%32
    }
}

// ---------------- Kernel 2: combine + top-k select (fused) ----------------
#define C_THREADS 128
#define C_JPT     32

__global__ void __launch_bounds__(C_THREADS)
hv_combine_kernel(const float* __restrict__ sig, float* __restrict__ out)
{
    const int b = blockIdx.x;
    const int t = threadIdx.x;          // column index 0..127 (word w = t)

    __shared__ int sseed[NSAMP];
    __shared__ int shist[51];
    __shared__ int sscan[C_THREADS];
    __shared__ int sT, sQuota;

    if (t < NSAMP) {
        const int i   = t;
        const int idx = (i * (LSIG - 1)) / (NSAMP - 1);   // trunc of f32 linspace
        const float s = sig[(size_t)b * LSIG + idx];
        const int val = __float2int_rn(s * 1000.0f);       // jnp.round RNE
        sseed[i] = i ^ val;                                 // in [0,1024)
    }
    if (t < 51) shist[t] = 0;
    __syncthreads();

    // Bit-sliced accumulation: two 6-plane ripple counters (50 words each).
    uint32_t pA0=0,pA1=0,pA2=0,pA3=0,pA4=0,pA5=0;
    uint32_t pB0=0,pB1=0,pB2=0,pB3=0,pB4=0,pB5=0;

#pragma unroll 5
    for (int i = 0; i < NSAMP; i += 2) {
        uint32_t ca = g_hv[(size_t)sseed[i]     * WPR + t];
        uint32_t cb = g_hv[(size_t)sseed[i + 1] * WPR + t];
        uint32_t s;
        s = pA0 ^ ca; ca &= pA0; pA0 = s;
        s = pA1 ^ ca; ca &= pA1; pA1 = s;
        s = pA2 ^ ca; ca &= pA2; pA2 = s;
        s = pA3 ^ ca; ca &= pA3; pA3 = s;
        s = pA4 ^ ca; ca &= pA4; pA4 = s;
        pA5 ^= ca;
        s = pB0 ^ cb; cb &= pB0; pB0 = s;
        s = pB1 ^ cb; cb &= pB1; pB1 = s;
        s = pB2 ^ cb; cb &= pB2; pB2 = s;
        s = pB3 ^ cb; cb &= pB3; pB3 = s;
        s = pB4 ^ cb; cb &= pB4; pB4 = s;
        pB5 ^= cb;
    }

    // Merge A + B bit-parallel -> 7 result planes
    uint32_t r0,r1,r2,r3,r4,r5,r6, c;
    r0 = pA0 ^ pB0;              c  = pA0 & pB0;
    r1 = pA1 ^ pB1 ^ c;          c  = (pA1 & pB1) | (c & (pA1 ^ pB1));
    r2 = pA2 ^ pB2 ^ c;          c  = (pA2 & pB2) | (c & (pA2 ^ pB2));
    r3 = pA3 ^ pB3 ^ c;          c  = (pA3 & pB3) | (c & (pA3 ^ pB3));
    r4 = pA4 ^ pB4 ^ c;          c  = (pA4 & pB4) | (c & (pA4 ^ pB4));
    r5 = pA5 ^ pB5 ^ c;          c  = (pA5 & pB5) | (c & (pA5 ^ pB5));
    r6 = c;

    // Per-position counts n (of msb=1 i.e. -1 contributions); cval = 100 - 2n
    int cval[C_JPT];
#pragma unroll
    for (int l = 0; l < C_JPT; l++) {
        int n =  (int)((r0 >> l) & 1u)
              + ((int)((r1 >> l) & 1u) << 1)
              + ((int)((r2 >> l) & 1u) << 2)
              + ((int)((r3 >> l) & 1u) << 3)
              + ((int)((r4 >> l) & 1u) << 4)
              + ((int)((r5 >> l) & 1u) << 5)
              + ((int)((r6 >> l) & 1u) << 6);
        cval[l] = NSAMP - 2 * n;
    }

    // ---- histogram of |c|/2 (bins 0..50) ----
#pragma unroll
    for (int q = 0; q < C_JPT; q++) {
        int a = cval[q] < 0 ? -cval[q] : cval[q];
        atomicAdd(&shist[a >> 1], 1);
    }
    __syncthreads();

    // ---- threshold T and tie quota ----
    if (t == 0) {
        int cum = 0, T = 0, quota = 0;
        for (int v = 50; v >= 0; v--) {
            int h = shist[v];
            if (cum + h >= KSEL) { T = v * 2; quota = KSEL - cum; break; }
            cum += h;
        }
        sT = T; sQuota = quota;
    }
    __syncthreads();
    const int T = sT, quota = sQuota;

    // ---- ordered block scan of (|c|==T) for stable index tie-break ----
    int eq = 0;
#pragma unroll
    for (int q = 0; q < C_JPT; q++) {
        int a = cval[q] < 0 ? -cval[q] : cval[q];
        eq += (a == T);
    }
    sscan[t] = eq;
    __syncthreads();
    for (int off = 1; off < C_THREADS; off <<= 1) {
        int v = sscan[t];
        int add = (t >= off) ? sscan[t - off] : 0;
        __syncthreads();
        sscan[t] = v + add;
        __syncthreads();
    }
    int rank = sscan[t] - eq;

    // ---- write output (j = t*32 + q, contiguous per thread) ----
    float* orow = out + (size_t)b * DIMV + t * C_JPT;
#pragma unroll
    for (int q = 0; q < C_JPT; q++) {
        const int cc = cval[q];
        const int a  = cc < 0 ? -cc : cc;
        float v = 0.0f;
        if (a > T) {
            v = (cc > 0) ? 1.0f : -1.0f;
        } else if (a == T) {
            if (rank < quota) v = (cc > 0) ? 1.0f : ((cc < 0) ? -1.0f : 0.0f);
            rank++;
        }
        orow[q] = v;
    }
}

extern "C" void kernel_launch(void* const* d_in, const int* in_sizes, int n_in,
                              void* d_out, int out_size)
{
    const float* sig = (const float*)d_in[0];
    float* out = (float*)d_out;
    const int B = in_sizes[0] / LSIG;   // 512
    hv_table_kernel<<<NSEEDS, 256>>>();
    hv_combine_kernel<<<B, C_THREADS>>>(sig, out);
}

// round 5
// speedup vs baseline: 19.9785x; 1.1323x over previous
#include <cuda_runtime.h>
#include <stdint.h>

// HypervectorEngine: 512x8192 f32 -> 512x4096 f32 sparse sign output.
// seed = i ^ round(sig*1000) in [0,1024) -> only 1024 distinct hypervectors.
// K1: build bit-packed sign table (4.2M threefry, pipe-balanced IMAD/alu).
// K2: per-row combine via bit-sliced counters, 2-way sample split for occupancy,
//     fused histogram/threshold/stable-rank select.
// RNG: JAX partitionable threefry, word_j = o0 ^ o1 of threefry(key,(0,j)). (verified R2)

#define NSAMP   100
#define HSAMP   50
#define DIMV    4096
#define KSEL    2048
#define LSIG    8192
#define NSEEDS  1024
#define WPR     (DIMV / 32)        // 128 packed words per hypervector

__device__ uint32_t g_hv[NSEEDS * WPR];

// Force add onto the FMA pipe: d = a*one + b ('one' runtime-opaque).
__device__ __forceinline__ uint32_t addi(uint32_t a, uint32_t b, uint32_t one) {
    uint32_t d;
    asm("mad.lo.u32 %0, %1, %2, %3;" : "=r"(d) : "r"(a), "r"(one), "r"(b));
    return d;
}

// JAX threefry2x32, key (0,42), counter (0,c1) -> derived key (fold_in). Cold path.
__device__ __forceinline__ void threefry_key(uint32_t c1, uint32_t& o0, uint32_t& o1)
{
    const uint32_t k0 = 0u, k1 = 42u, k2 = 0u ^ 42u ^ 0x1BD11BDAu;
    uint32_t x0 = k0, x1 = c1 + k1;
    #define R(r) { x0 += x1; x1 = __funnelshift_l(x1, x1, r); x1 ^= x0; }
    R(13) R(15) R(26) R(6)  x0 += k1; x1 += k2 + 1u;
    R(17) R(29) R(16) R(24) x0 += k2; x1 += k0 + 2u;
    R(13) R(15) R(26) R(6)  x0 += k0; x1 += k1 + 3u;
    R(17) R(29) R(16) R(24) x0 += k1; x1 += k2 + 4u;
    R(13) R(15) R(26) R(6)
    o0 = x0 + k2; o1 = x1 + k0 + 5u;
    #undef R
}

// ---------------- Kernel 1: build hypervector sign table ----------------
__global__ void __launch_bounds__(256)
hv_table_kernel(uint32_t one)
{
    const int seed = blockIdx.x;
    const int t    = threadIdx.x;
    const int lane = t & 31;
    const int wrp  = t >> 5;           // 0..7

    __shared__ uint32_t sk0, sk1;
    if (t == 0) {
        uint32_t o0, o1;
        threefry_key((uint32_t)seed, o0, o1);
        sk0 = o0; sk1 = o1;
    }
    __syncthreads();
    const uint32_t k0 = sk0, k1 = sk1, k2 = k0 ^ k1 ^ 0x1BD11BDAu;
    const uint32_t k2p1 = k2 + 1u, k0p2 = k0 + 2u, k1p3 = k1 + 3u;
    const uint32_t k2p4 = k2 + 4u, k0p5 = k0 + 5u;
    const uint32_t k1t  = k1 + (uint32_t)t;

    uint32_t* dst = g_hv + (size_t)seed * WPR;
#pragma unroll
    for (int p = 0; p < DIMV / 256; p++) {       // 16 hashes per thread
        uint32_t x0 = k0;
        uint32_t x1 = addi(k1t, (uint32_t)(p * 256), one);
        #define RB(r) { x0 = addi(x0, x1, one); x1 = __funnelshift_l(x1, x1, r); x1 ^= x0; }
        RB(13) RB(15) RB(26) RB(6)
        x0 = addi(x0, k1, one); x1 = addi(x1, k2p1, one);
        RB(17) RB(29) RB(16) RB(24)
        x0 = addi(x0, k2, one); x1 = addi(x1, k0p2, one);
        RB(13) RB(15) RB(26) RB(6)
        x0 = addi(x0, k0, one); x1 = addi(x1, k1p3, one);
        RB(17) RB(29) RB(16) RB(24)
        x0 = addi(x0, k1, one); x1 = addi(x1, k2p4, one);
        RB(13) RB(15) RB(26) RB(6)
        #undef RB
        const uint32_t o0 = addi(x0, k2, one);
        const uint32_t o1 = addi(x1, k0p5, one);
        const uint32_t word = __ballot_sync(0xFFFFFFFFu, (int)((o0 ^ o1) >> 31));
        if (lane == 0) dst[p * 8 + wrp] = word;
    }
}

// ---------------- Kernel 2: combine + top-k select (fused) ----------------
#define C_THREADS 256
#define C_BPT     16               // bits (output elems) per thread in epilogue

__global__ void __launch_bounds__(C_THREADS)
hv_combine_kernel(const float* __restrict__ sig, float* __restrict__ out)
{
    const int b = blockIdx.x;
    const int t = threadIdx.x;

    __shared__ int      sseed[NSAMP];
    __shared__ uint32_t spl[2][6][WPR];   // [half][plane][word], 6 KB
    __shared__ int      shist[51];
    __shared__ int      sscan[C_THREADS];
    __shared__ int      sT, sQuota;

    if (t < NSAMP) {
        const int i   = t;
        const int idx = (i * (LSIG - 1)) / (NSAMP - 1);   // trunc of f32 linspace
        const float s = sig[(size_t)b * LSIG + idx];
        const int val = __float2int_rn(s * 1000.0f);      // jnp.round RNE
        sseed[i] = i ^ val;                                // in [0,1024)
    }
    if (t < 51) shist[t] = 0;
    __syncthreads();

    // ---- accumulate: thread t handles word w for sample-half h ----
    {
        const int w = t & (WPR - 1);
        const int h = t >> 7;                  // 0 or 1
        const int ibase = h * HSAMP;

        uint32_t p0=0,p1=0,p2=0,p3=0,p4=0,p5=0;
#pragma unroll 10
        for (int i = 0; i < HSAMP; i++) {
            uint32_t ca = g_hv[(size_t)sseed[ibase + i] * WPR + w];
            uint32_t s;
            s = p0 ^ ca; ca &= p0; p0 = s;
            s = p1 ^ ca; ca &= p1; p1 = s;
            s = p2 ^ ca; ca &= p2; p2 = s;
            s = p3 ^ ca; ca &= p3; p3 = s;
            s = p4 ^ ca; ca &= p4; p4 = s;
            p5 ^= ca;
        }
        spl[h][0][w] = p0; spl[h][1][w] = p1; spl[h][2][w] = p2;
        spl[h][3][w] = p3; spl[h][4][w] = p4; spl[h][5][w] = p5;
    }
    __syncthreads();

    // ---- merge halves + extract: thread t -> word w2 = t>>1, bits [hb*16, +16) ----
    const int w2 = t >> 1;
    const int hb = t & 1;

    uint32_t a0 = spl[0][0][w2], a1 = spl[0][1][w2], a2 = spl[0][2][w2];
    uint32_t a3 = spl[0][3][w2], a4 = spl[0][4][w2], a5 = spl[0][5][w2];
    uint32_t b0 = spl[1][0][w2], b1 = spl[1][1][w2], b2 = spl[1][2][w2];
    uint32_t b3 = spl[1][3][w2], b4 = spl[1][4][w2], b5 = spl[1][5][w2];

    uint32_t r0,r1,r2,r3,r4,r5,r6, c;
    r0 = a0 ^ b0;       c = a0 & b0;
    r1 = a1 ^ b1 ^ c;   c = (a1 & b1) | (c & (a1 ^ b1));
    r2 = a2 ^ b2 ^ c;   c = (a2 & b2) | (c & (a2 ^ b2));
    r3 = a3 ^ b3 ^ c;   c = (a3 & b3) | (c & (a3 ^ b3));
    r4 = a4 ^ b4 ^ c;   c = (a4 & b4) | (c & (a4 ^ b4));
    r5 = a5 ^ b5 ^ c;   c = (a5 & b5) | (c & (a5 ^ b5));
    r6 = c;

    int cval[C_BPT];
#pragma unroll
    for (int q = 0; q < C_BPT; q++) {
        const int l = hb * 16 + q;
        int n =  (int)((r0 >> l) & 1u)
              + ((int)((r1 >> l) & 1u) << 1)
              + ((int)((r2 >> l) & 1u) << 2)
              + ((int)((r3 >> l) & 1u) << 3)
              + ((int)((r4 >> l) & 1u) << 4)
              + ((int)((r5 >> l) & 1u) << 5)
              + ((int)((r6 >> l) & 1u) << 6);
        cval[q] = NSAMP - 2 * n;     // combined[j], j = t*16 + q
    }

    // ---- histogram of |c|/2 (bins 0..50) ----
#pragma unroll
    for (int q = 0; q < C_BPT; q++) {
        int a = cval[q] < 0 ? -cval[q] : cval[q];
        atomicAdd(&shist[a >> 1], 1);
    }
    __syncthreads();

    // ---- threshold T and tie quota ----
    if (t == 0) {
        int cum = 0, T = 0, quota = 0;
        for (int v = 50; v >= 0; v--) {
            int h = shist[v];
            if (cum + h >= KSEL) { T = v * 2; quota = KSEL - cum; break; }
            cum += h;
        }
        sT = T; sQuota = quota;
    }
    __syncthreads();
    const int T = sT, quota = sQuota;

    // ---- ordered block scan of (|c|==T): stable index tie-break ----
    int eq = 0;
#pragma unroll
    for (int q = 0; q < C_BPT; q++) {
        int a = cval[q] < 0 ? -cval[q] : cval[q];
        eq += (a == T);
    }
    sscan[t] = eq;
    __syncthreads();
    for (int off = 1; off < C_THREADS; off <<= 1) {
        int v = sscan[t];
        int add = (t >= off) ? sscan[t - off] : 0;
        __syncthreads();
        sscan[t] = v + add;
        __syncthreads();
    }
    int rank = sscan[t] - eq;

    // ---- write output (j = t*16 + q) ----
    float* orow = out + (size_t)b * DIMV + t * C_BPT;
#pragma unroll
    for (int q = 0; q < C_BPT; q++) {
        const int cc = cval[q];
        const int a  = cc < 0 ? -cc : cc;
        float v = 0.0f;
        if (a > T) {
            v = (cc > 0) ? 1.0f : -1.0f;
        } else if (a == T) {
            if (rank < quota) v = (cc > 0) ? 1.0f : ((cc < 0) ? -1.0f : 0.0f);
            rank++;
        }
        orow[q] = v;
    }
}

extern "C" void kernel_launch(void* const* d_in, const int* in_sizes, int n_in,
                              void* d_out, int out_size)
{
    const float* sig = (const float*)d_in[0];
    float* out = (float*)d_out;
    const int B = in_sizes[0] / LSIG;   // 512
    hv_table_kernel<<<NSEEDS, 256>>>(1u);
    hv_combine_kernel<<<B, C_THREADS>>>(sig, out);
}